// round 2
// baseline (speedup 1.0000x reference)
#include <cuda_runtime.h>
#include <math.h>

// Problem constants
#define Nn 16
#define Ee 512
#define Dd 1024
#define Hh 8
#define Tt 2
#define Oo 128
#define HT (Hh*Tt)          // 16
#define HO (Hh*Oo)          // 1024
#define NEGV (-9000000000000000.0f)

// ---------------- scratch (device globals; no allocation allowed) ----------
__device__ float g_h[(size_t)HT * Nn * Ee * Oo];      // 64 MB  [ht][n][e][o]
__device__ float g_v1[HT * Nn * Oo];                  // g1*a_src  [ht][n][o]
__device__ float g_v2[HT * Nn * Oo];                  // g2*a_dst
__device__ float g_s1[HT * Nn * Ee];                  // [ht][n][e]
__device__ float g_s2[HT * Nn * Ee];
__device__ float g_coefs[(size_t)Hh * Nn * Ee * Ee];  // 128 MB [h][n][i][j]

// ============================================================================
// Kernel 1: h[ht][n*E+e][o] = sum_d input[n,e,d] * W[ht][d][o]
// Batched SGEMM: 16 batches of [8192 x 1024] @ [1024 x 128]
// BM=128 BN=128 BK=16, 256 threads, 8x8 microtile
// ============================================================================
__global__ __launch_bounds__(256) void gemm1_kernel(const float* __restrict__ A,
                                                    const float* __restrict__ Wp) {
    int ht = blockIdx.z;
    const float* B = Wp + (size_t)ht * Dd * Oo;
    float* C = g_h + (size_t)ht * (Nn * Ee) * Oo;
    int m0 = blockIdx.x * 128;

    __shared__ float As[16][128];
    __shared__ float Bs[16][128];

    int tid = threadIdx.x;
    int ty = tid >> 4, tx = tid & 15;
    float acc[8][8] = {};

    for (int k0 = 0; k0 < Dd; k0 += 16) {
        // A tile: 128 rows x 16 cols, store transposed into As[k][m]
#pragma unroll
        for (int l = 0; l < 2; l++) {
            int idx = tid * 2 + l;
            int row = idx >> 2, c4 = idx & 3;
            float4 v = *(const float4*)&A[(size_t)(m0 + row) * Dd + k0 + c4 * 4];
            As[c4 * 4 + 0][row] = v.x;
            As[c4 * 4 + 1][row] = v.y;
            As[c4 * 4 + 2][row] = v.z;
            As[c4 * 4 + 3][row] = v.w;
        }
        // B tile: 16 rows x 128 cols
#pragma unroll
        for (int l = 0; l < 2; l++) {
            int idx = tid * 2 + l;
            int row = idx >> 5, c4 = idx & 31;
            *(float4*)&Bs[row][c4 * 4] =
                *(const float4*)&B[(size_t)(k0 + row) * Oo + c4 * 4];
        }
        __syncthreads();
#pragma unroll
        for (int kk = 0; kk < 16; kk++) {
            float4 a0 = *(float4*)&As[kk][ty * 8];
            float4 a1 = *(float4*)&As[kk][ty * 8 + 4];
            float4 b0 = *(float4*)&Bs[kk][tx * 8];
            float4 b1 = *(float4*)&Bs[kk][tx * 8 + 4];
            float ra[8] = {a0.x, a0.y, a0.z, a0.w, a1.x, a1.y, a1.z, a1.w};
            float rb[8] = {b0.x, b0.y, b0.z, b0.w, b1.x, b1.y, b1.z, b1.w};
#pragma unroll
            for (int i = 0; i < 8; i++)
#pragma unroll
                for (int j = 0; j < 8; j++) acc[i][j] += ra[i] * rb[j];
        }
        __syncthreads();
    }
#pragma unroll
    for (int i = 0; i < 8; i++)
#pragma unroll
        for (int j = 0; j < 8; j++)
            C[(size_t)(m0 + ty * 8 + i) * Oo + tx * 8 + j] = acc[i][j];
}

// ============================================================================
// Kernel 2: query-gate MLP.  Per (ht, n):
//   tmp = relu(qvec[n] @ qW1[ht])          (256)
//   g   = sigmoid(tmp @ qW2[ht])           (256)
//   v1[o] = g[o]     * a_src[ht][o]  (o<128)
//   v2[o] = g[o+128] * a_dst[ht][o]
// ============================================================================
__global__ __launch_bounds__(256) void gate_kernel(const float* __restrict__ qvec,
                                                   const float* __restrict__ qW1,
                                                   const float* __restrict__ qW2,
                                                   const float* __restrict__ a_src,
                                                   const float* __restrict__ a_dst) {
    int n = blockIdx.x;
    int ht = blockIdx.y;
    __shared__ float qv[1024];
    __shared__ float tmp[256];
    int tid = threadIdx.x;

    for (int i = tid; i < 1024; i += 256) qv[i] = qvec[n * 1024 + i];
    __syncthreads();

    const float* w1 = qW1 + (size_t)ht * 1024 * 256;
    float s = 0.f;
    for (int q = 0; q < 1024; q++) s += qv[q] * w1[(size_t)q * 256 + tid];
    tmp[tid] = fmaxf(s, 0.f);
    __syncthreads();

    const float* w2 = qW2 + (size_t)ht * 256 * 256;
    float s2 = 0.f;
    for (int c = 0; c < 256; c++) s2 += tmp[c] * w2[c * 256 + tid];
    float g = 1.f / (1.f + expf(-s2));

    int base = (ht * Nn + n) * Oo;
    if (tid < 128) g_v1[base + tid] = g * a_src[ht * Oo + tid];
    else           g_v2[base + (tid - 128)] = g * a_dst[ht * Oo + (tid - 128)];
}

// ============================================================================
// Kernel 3: s1[ht][n][e] = dot(h[ht][n][e][:], v1[ht][n][:]), same for s2.
// One block per (ht,n); 8 warps, each warp handles e stripes.
// ============================================================================
__global__ __launch_bounds__(256) void s12_kernel() {
    int b = blockIdx.x;  // ht*Nn + n, 256 blocks
    __shared__ float sv1[128], sv2[128];
    int tid = threadIdx.x;
    if (tid < 128) sv1[tid] = g_v1[b * 128 + tid];
    else           sv2[tid - 128] = g_v2[b * 128 + (tid - 128)];
    __syncthreads();

    int warp = tid >> 5, lane = tid & 31;
    const float* hb = g_h + (size_t)b * Ee * Oo;
    for (int e = warp; e < Ee; e += 8) {
        const float* hr = hb + (size_t)e * Oo;
        float a1 = 0.f, a2 = 0.f;
#pragma unroll
        for (int c = lane; c < 128; c += 32) {
            float hv = hr[c];
            a1 += hv * sv1[c];
            a2 += hv * sv2[c];
        }
#pragma unroll
        for (int off = 16; off; off >>= 1) {
            a1 += __shfl_down_sync(0xffffffffu, a1, off);
            a2 += __shfl_down_sync(0xffffffffu, a2, off);
        }
        if (lane == 0) {
            g_s1[b * Ee + e] = a1;
            g_s2[b * Ee + e] = a2;
        }
    }
}

// ============================================================================
// Kernel 4a: scores + softmax -> coefs[h][n][i][j]
// One block per (i, n); 512 threads, j = tid, all 8 heads in registers.
// ============================================================================
__global__ __launch_bounds__(512) void attn_kernel(const int* __restrict__ adj) {
    int i = blockIdx.x;
    int n = blockIdx.y;
    int tid = threadIdx.x;  // j

    __shared__ float s2s[HT][Ee];   // 32 KB
    __shared__ float s1v[HT];
    __shared__ float redm[16], reds[16];

    if (tid < HT) s1v[tid] = g_s1[(tid * Nn + n) * Ee + i];
    for (int idx = tid; idx < HT * Ee; idx += 512) {
        int ht = idx >> 9, j = idx & 511;
        s2s[ht][j] = g_s2[(ht * Nn + n) * Ee + j];
    }
    int a = adj[((size_t)n * Ee + i) * Ee + tid];
    __syncthreads();

    float sc[Hh];
#pragma unroll
    for (int h = 0; h < Hh; h++) {
        if (a == 0) sc[h] = NEGV;
        else {
            int ht = h * Tt + (a - 1);
            float x = s1v[ht] + s2s[ht][tid];
            sc[h] = x > 0.f ? x : 0.2f * x;
        }
    }

    int lane = tid & 31, warp = tid >> 5;
    for (int h = 0; h < Hh; h++) {
        // row max
        float m = sc[h];
#pragma unroll
        for (int off = 16; off; off >>= 1)
            m = fmaxf(m, __shfl_xor_sync(0xffffffffu, m, off));
        if (lane == 0) redm[warp] = m;
        __syncthreads();
        if (tid == 0) {
            float mm = redm[0];
            for (int k = 1; k < 16; k++) mm = fmaxf(mm, redm[k]);
            redm[0] = mm;
        }
        __syncthreads();
        float rowmax = redm[0];
        float e = expf(sc[h] - rowmax);
        float s = e;
#pragma unroll
        for (int off = 16; off; off >>= 1)
            s += __shfl_xor_sync(0xffffffffu, s, off);
        if (lane == 0) reds[warp] = s;
        __syncthreads();
        if (tid == 0) {
            float ss = 0.f;
            for (int k = 0; k < 16; k++) ss += reds[k];
            reds[0] = ss;
        }
        __syncthreads();
        float tot = reds[0];
        g_coefs[(((size_t)h * Nn + n) * Ee + i) * Ee + tid] = e / tot;
        __syncthreads();  // protect redm/reds for next h
    }
}

// ============================================================================
// Kernel 4b: out[n][j][h*128+o] = relu( sum_i coefs[h][n][i][j] * hlast[h][n][i][o] )
// Batched SGEMM (A transposed): per (h,n): M=512(j) N=128(o) K=512(i)
// ============================================================================
__global__ __launch_bounds__(256) void gemm2_kernel(float* __restrict__ out) {
    int z = blockIdx.z;
    int h = z >> 4, n = z & 15;
    const float* P = g_coefs + ((size_t)(h * Nn + n)) * Ee * Ee;          // [i][j]
    const float* B = g_h + ((size_t)((h * Tt + 1) * Nn + n)) * Ee * Oo;   // h_last [i][o]
    int m0 = blockIdx.x * 128;

    __shared__ float As[16][128];
    __shared__ float Bs[16][128];

    int tid = threadIdx.x;
    int ty = tid >> 4, tx = tid & 15;
    float acc[8][8] = {};

    for (int k0 = 0; k0 < Ee; k0 += 16) {
        // As[kk][mm] = P[(k0+kk)*Ee + m0+mm]  (transposed access, coalesced rows)
#pragma unroll
        for (int l = 0; l < 2; l++) {
            int idx = tid * 2 + l;
            int kk = idx >> 5, m4 = idx & 31;
            *(float4*)&As[kk][m4 * 4] =
                *(const float4*)&P[(size_t)(k0 + kk) * Ee + m0 + m4 * 4];
        }
#pragma unroll
        for (int l = 0; l < 2; l++) {
            int idx = tid * 2 + l;
            int kk = idx >> 5, c4 = idx & 31;
            *(float4*)&Bs[kk][c4 * 4] =
                *(const float4*)&B[(size_t)(k0 + kk) * Oo + c4 * 4];
        }
        __syncthreads();
#pragma unroll
        for (int kk = 0; kk < 16; kk++) {
            float4 a0 = *(float4*)&As[kk][ty * 8];
            float4 a1 = *(float4*)&As[kk][ty * 8 + 4];
            float4 b0 = *(float4*)&Bs[kk][tx * 8];
            float4 b1 = *(float4*)&Bs[kk][tx * 8 + 4];
            float ra[8] = {a0.x, a0.y, a0.z, a0.w, a1.x, a1.y, a1.z, a1.w};
            float rb[8] = {b0.x, b0.y, b0.z, b0.w, b1.x, b1.y, b1.z, b1.w};
#pragma unroll
            for (int i = 0; i < 8; i++)
#pragma unroll
                for (int j = 0; j < 8; j++) acc[i][j] += ra[i] * rb[j];
        }
        __syncthreads();
    }
#pragma unroll
    for (int i = 0; i < 8; i++) {
        int j = m0 + ty * 8 + i;
#pragma unroll
        for (int jj = 0; jj < 8; jj++) {
            int o = tx * 8 + jj;
            out[(size_t)n * Ee * HO + (size_t)j * HO + h * Oo + o] =
                fmaxf(acc[i][jj], 0.f);
        }
    }
}

// ============================================================================
extern "C" void kernel_launch(void* const* d_in, const int* in_sizes, int n_in,
                              void* d_out, int out_size) {
    const float* input_state = (const float*)d_in[0];
    const int*   adj         = (const int*)d_in[1];
    // d_in[2] = entity_mask (unused by the reference)
    const float* query_vec   = (const float*)d_in[3];
    const float* W           = (const float*)d_in[4];
    const float* a_src       = (const float*)d_in[5];
    const float* a_dst       = (const float*)d_in[6];
    const float* qW1         = (const float*)d_in[7];
    const float* qW2         = (const float*)d_in[8];
    float* out = (float*)d_out;

    gemm1_kernel<<<dim3(64, 1, HT), 256>>>(input_state, W);
    gate_kernel<<<dim3(Nn, HT), 256>>>(query_vec, qW1, qW2, a_src, a_dst);
    s12_kernel<<<HT * Nn, 256>>>();
    attn_kernel<<<dim3(Ee, Nn), 512>>>(adj);
    gemm2_kernel<<<dim3(4, 1, Hh * Nn), 256>>>(out);
}

// round 3
// speedup vs baseline: 1.3769x; 1.3769x over previous
#include <cuda_runtime.h>
#include <math.h>

// Problem constants
#define Nn 16
#define Ee 512
#define Dd 1024
#define Hh 8
#define Tt 2
#define Oo 128
#define HT (Hh*Tt)          // 16
#define HO (Hh*Oo)          // 1024
#define NEGV (-9000000000000000.0f)

// ---------------- scratch (device globals) ----------------------------------
__device__ float g_h[(size_t)Hh * Nn * Ee * Oo];      // 32 MB  h_last [h][n][e][o]
__device__ float g_v1[HT * Nn * Oo];                  // g1*a_src  [ht][n][o]
__device__ float g_v2[HT * Nn * Oo];                  // g2*a_dst
__device__ float g_u[(size_t)Nn * Dd * 32];           // 2 MB [n][d][c] c: 0-15 u1(ht), 16-31 u2(ht)
__device__ float g_s1[HT * Nn * Ee];                  // [ht][n][e]
__device__ float g_s2[HT * Nn * Ee];
__device__ float g_coefs[(size_t)Hh * Nn * Ee * Ee];  // 128 MB [h][n][i][j]

// ============================================================================
// Kernel 1: h_last[h][n*E+e][o] = sum_d input[n,e,d] * W[h, T-1][d][o]
// 8 batches of [8192 x 1024] @ [1024 x 128]; BM=BN=128 BK=16, double-buffered.
// ============================================================================
__global__ __launch_bounds__(256) void gemm1_kernel(const float* __restrict__ A,
                                                    const float* __restrict__ Wp) {
    int h = blockIdx.z;
    const float* B = Wp + (size_t)(h * Tt + (Tt - 1)) * Dd * Oo;
    float* C = g_h + (size_t)h * (Nn * Ee) * Oo;
    int m0 = blockIdx.x * 128;

    __shared__ float As[2][16][128];
    __shared__ float Bs[2][16][128];

    int tid = threadIdx.x;
    int ty = tid >> 4, tx = tid & 15;
    float acc[8][8] = {};

    int i0 = tid * 2, i1 = tid * 2 + 1;
    int ar0 = i0 >> 2, ac0 = i0 & 3;
    int ar1 = i1 >> 2, ac1 = i1 & 3;
    int br0 = i0 >> 5, bc0 = i0 & 31;
    int br1 = i1 >> 5, bc1 = i1 & 31;

    const float* Ab = A + (size_t)m0 * Dd;

    // preload k0 = 0 into buffer 0
    float4 rA0 = *(const float4*)&Ab[(size_t)ar0 * Dd + ac0 * 4];
    float4 rA1 = *(const float4*)&Ab[(size_t)ar1 * Dd + ac1 * 4];
    float4 rB0 = *(const float4*)&B[(size_t)br0 * Oo + bc0 * 4];
    float4 rB1 = *(const float4*)&B[(size_t)br1 * Oo + bc1 * 4];
    As[0][ac0*4+0][ar0]=rA0.x; As[0][ac0*4+1][ar0]=rA0.y; As[0][ac0*4+2][ar0]=rA0.z; As[0][ac0*4+3][ar0]=rA0.w;
    As[0][ac1*4+0][ar1]=rA1.x; As[0][ac1*4+1][ar1]=rA1.y; As[0][ac1*4+2][ar1]=rA1.z; As[0][ac1*4+3][ar1]=rA1.w;
    *(float4*)&Bs[0][br0][bc0*4] = rB0;
    *(float4*)&Bs[0][br1][bc1*4] = rB1;
    __syncthreads();

    for (int k0 = 0; k0 < Dd; k0 += 16) {
        int buf = (k0 >> 4) & 1;
        bool more = (k0 + 16) < Dd;
        if (more) {
            int kn = k0 + 16;
            rA0 = *(const float4*)&Ab[(size_t)ar0 * Dd + kn + ac0 * 4];
            rA1 = *(const float4*)&Ab[(size_t)ar1 * Dd + kn + ac1 * 4];
            rB0 = *(const float4*)&B[(size_t)(kn + br0) * Oo + bc0 * 4];
            rB1 = *(const float4*)&B[(size_t)(kn + br1) * Oo + bc1 * 4];
        }
#pragma unroll
        for (int kk = 0; kk < 16; kk++) {
            float4 a0 = *(float4*)&As[buf][kk][ty * 8];
            float4 a1 = *(float4*)&As[buf][kk][ty * 8 + 4];
            float4 b0 = *(float4*)&Bs[buf][kk][tx * 8];
            float4 b1 = *(float4*)&Bs[buf][kk][tx * 8 + 4];
            float ra[8] = {a0.x, a0.y, a0.z, a0.w, a1.x, a1.y, a1.z, a1.w};
            float rb[8] = {b0.x, b0.y, b0.z, b0.w, b1.x, b1.y, b1.z, b1.w};
#pragma unroll
            for (int i = 0; i < 8; i++)
#pragma unroll
                for (int j = 0; j < 8; j++) acc[i][j] += ra[i] * rb[j];
        }
        if (more) {
            int nb = buf ^ 1;
            As[nb][ac0*4+0][ar0]=rA0.x; As[nb][ac0*4+1][ar0]=rA0.y; As[nb][ac0*4+2][ar0]=rA0.z; As[nb][ac0*4+3][ar0]=rA0.w;
            As[nb][ac1*4+0][ar1]=rA1.x; As[nb][ac1*4+1][ar1]=rA1.y; As[nb][ac1*4+2][ar1]=rA1.z; As[nb][ac1*4+3][ar1]=rA1.w;
            *(float4*)&Bs[nb][br0][bc0*4] = rB0;
            *(float4*)&Bs[nb][br1][bc1*4] = rB1;
            __syncthreads();
        }
    }
#pragma unroll
    for (int i = 0; i < 8; i++)
#pragma unroll
        for (int j = 0; j < 8; j++)
            C[(size_t)(m0 + ty * 8 + i) * Oo + tx * 8 + j] = acc[i][j];
}

// ============================================================================
// Kernel 2: query-gate MLP -> v1 = g1*a_src, v2 = g2*a_dst  (per ht,n)
// ============================================================================
__global__ __launch_bounds__(256) void gate_kernel(const float* __restrict__ qvec,
                                                   const float* __restrict__ qW1,
                                                   const float* __restrict__ qW2,
                                                   const float* __restrict__ a_src,
                                                   const float* __restrict__ a_dst) {
    int n = blockIdx.x;
    int ht = blockIdx.y;
    __shared__ float qv[1024];
    __shared__ float tmp[256];
    int tid = threadIdx.x;

    for (int i = tid; i < 1024; i += 256) qv[i] = qvec[n * 1024 + i];
    __syncthreads();

    const float* w1 = qW1 + (size_t)ht * 1024 * 256;
    float s = 0.f;
    for (int q = 0; q < 1024; q++) s += qv[q] * w1[(size_t)q * 256 + tid];
    tmp[tid] = fmaxf(s, 0.f);
    __syncthreads();

    const float* w2 = qW2 + (size_t)ht * 256 * 256;
    float s2 = 0.f;
    for (int c = 0; c < 256; c++) s2 += tmp[c] * w2[c * 256 + tid];
    float g = 1.f / (1.f + expf(-s2));

    int base = (ht * Nn + n) * Oo;
    if (tid < 128) g_v1[base + tid] = g * a_src[ht * Oo + tid];
    else           g_v2[base + (tid - 128)] = g * a_dst[ht * Oo + (tid - 128)];
}

// ============================================================================
// Kernel 3: u[n][d][ht]    = sum_o W[ht][d][o] * v1[ht][n][o]
//           u[n][d][16+ht] = sum_o W[ht][d][o] * v2[ht][n][o]
// One block per (n, ht); warp per d row.
// ============================================================================
__global__ __launch_bounds__(256) void uvec_kernel(const float* __restrict__ Wp) {
    int n = blockIdx.x, ht = blockIdx.y;
    __shared__ float v1s[128], v2s[128];
    int tid = threadIdx.x;
    if (tid < 128) v1s[tid] = g_v1[(ht * Nn + n) * Oo + tid];
    else           v2s[tid - 128] = g_v2[(ht * Nn + n) * Oo + (tid - 128)];
    __syncthreads();

    int warp = tid >> 5, lane = tid & 31;
    const float* Wh = Wp + (size_t)ht * Dd * Oo;
    for (int d = warp; d < Dd; d += 8) {
        const float* wr = Wh + (size_t)d * Oo;
        float s1 = 0.f, s2 = 0.f;
#pragma unroll
        for (int c = lane; c < 128; c += 32) {
            float w = wr[c];
            s1 += w * v1s[c];
            s2 += w * v2s[c];
        }
#pragma unroll
        for (int off = 16; off; off >>= 1) {
            s1 += __shfl_down_sync(0xffffffffu, s1, off);
            s2 += __shfl_down_sync(0xffffffffu, s2, off);
        }
        if (lane == 0) {
            g_u[((size_t)n * Dd + d) * 32 + ht] = s1;
            g_u[((size_t)n * Dd + d) * 32 + 16 + ht] = s2;
        }
    }
}

// ============================================================================
// Kernel 4: S[n] = input[n] (E x D) @ U[n] (D x 32)  -> g_s1/g_s2
// Block per (e-tile of 64, n). 256 threads: thread -> (e = tid/4, 8 of 32 cols)
// ============================================================================
__global__ __launch_bounds__(256) void s12_kernel(const float* __restrict__ A) {
    int e0 = blockIdx.x * 64;
    int n = blockIdx.y;
    __shared__ float inT[64][68];
    __shared__ float Ut[64][36];

    int tid = threadIdx.x;
    int e = tid >> 2, g = tid & 3;
    float acc[8] = {};

    for (int d0 = 0; d0 < Dd; d0 += 64) {
#pragma unroll
        for (int l = 0; l < 4; l++) {
            int fid = tid + l * 256;
            int row = fid >> 4, c4 = fid & 15;
            *(float4*)&inT[row][c4 * 4] =
                *(const float4*)&A[((size_t)n * Ee + e0 + row) * Dd + d0 + c4 * 4];
        }
#pragma unroll
        for (int l = 0; l < 2; l++) {
            int fid = tid + l * 256;
            int row = fid >> 3, c4 = fid & 7;
            *(float4*)&Ut[row][c4 * 4] =
                *(const float4*)&g_u[((size_t)n * Dd + d0 + row) * 32 + c4 * 4];
        }
        __syncthreads();
#pragma unroll 8
        for (int d = 0; d < 64; d++) {
            float iv = inT[e][d];
            float4 ua = *(float4*)&Ut[d][g * 8];
            float4 ub = *(float4*)&Ut[d][g * 8 + 4];
            acc[0] += iv * ua.x; acc[1] += iv * ua.y;
            acc[2] += iv * ua.z; acc[3] += iv * ua.w;
            acc[4] += iv * ub.x; acc[5] += iv * ub.y;
            acc[6] += iv * ub.z; acc[7] += iv * ub.w;
        }
        __syncthreads();
    }
#pragma unroll
    for (int k = 0; k < 8; k++) {
        int c = g * 8 + k;
        if (c < 16) g_s1[(c * Nn + n) * Ee + e0 + e] = acc[k];
        else        g_s2[((c - 16) * Nn + n) * Ee + e0 + e] = acc[k];
    }
}

// ============================================================================
// Kernel 5: scores + softmax -> coefs[h][n][i][j].  Warp-per-head, no block sync
// after the load phase.
// ============================================================================
__global__ __launch_bounds__(256) void attn_kernel(const int* __restrict__ adj) {
    int i = blockIdx.x;
    int n = blockIdx.y;
    int tid = threadIdx.x;

    __shared__ int   adjs[Ee];
    __shared__ float s2s[HT][Ee];   // 32 KB
    __shared__ float s1v[HT];

    adjs[tid]       = adj[((size_t)n * Ee + i) * Ee + tid];
    adjs[tid + 256] = adj[((size_t)n * Ee + i) * Ee + tid + 256];
    for (int idx = tid; idx < HT * Ee; idx += 256) {
        int ht = idx >> 9, j = idx & 511;
        s2s[ht][j] = g_s2[(ht * Nn + n) * Ee + j];
    }
    if (tid < HT) s1v[tid] = g_s1[(tid * Nn + n) * Ee + i];
    __syncthreads();

    int h = tid >> 5, lane = tid & 31;
    float sc[16];
    float m = -INFINITY;
#pragma unroll
    for (int k = 0; k < 16; k++) {
        int j = lane + k * 32;
        int a = adjs[j];
        float x;
        if (a == 0) x = NEGV;
        else {
            int ht = h * Tt + (a - 1);
            float v = s1v[ht] + s2s[ht][j];
            x = v > 0.f ? v : 0.2f * v;
        }
        sc[k] = x;
        m = fmaxf(m, x);
    }
#pragma unroll
    for (int off = 16; off; off >>= 1)
        m = fmaxf(m, __shfl_xor_sync(0xffffffffu, m, off));
    float sum = 0.f;
#pragma unroll
    for (int k = 0; k < 16; k++) {
        float e = __expf(sc[k] - m);
        sc[k] = e;
        sum += e;
    }
#pragma unroll
    for (int off = 16; off; off >>= 1)
        sum += __shfl_xor_sync(0xffffffffu, sum, off);
    float inv = 1.f / sum;
    float* dst = &g_coefs[(((size_t)h * Nn + n) * Ee + i) * Ee];
#pragma unroll
    for (int k = 0; k < 16; k++)
        dst[lane + k * 32] = sc[k] * inv;
}

// ============================================================================
// Kernel 6: out[n][j][h*128+o] = relu( sum_i coefs[h][n][i][j] * hlast[h][n][i][o] )
// Double-buffered; per (h,n): M=512(j) N=128(o) K=512(i)
// ============================================================================
__global__ __launch_bounds__(256) void gemm2_kernel(float* __restrict__ out) {
    int z = blockIdx.z;
    int h = z >> 4, n = z & 15;
    const float* P = g_coefs + ((size_t)(h * Nn + n)) * Ee * Ee;    // [i][j]
    const float* B = g_h + ((size_t)(h * Nn + n)) * Ee * Oo;        // h_last [i][o]
    int m0 = blockIdx.x * 128;

    __shared__ float As[2][16][128];
    __shared__ float Bs[2][16][128];

    int tid = threadIdx.x;
    int ty = tid >> 4, tx = tid & 15;
    float acc[8][8] = {};

    int i0 = tid * 2, i1 = tid * 2 + 1;
    int kr0 = i0 >> 5, mc0 = i0 & 31;
    int kr1 = i1 >> 5, mc1 = i1 & 31;

    float4 rA0 = *(const float4*)&P[(size_t)kr0 * Ee + m0 + mc0 * 4];
    float4 rA1 = *(const float4*)&P[(size_t)kr1 * Ee + m0 + mc1 * 4];
    float4 rB0 = *(const float4*)&B[(size_t)kr0 * Oo + mc0 * 4];
    float4 rB1 = *(const float4*)&B[(size_t)kr1 * Oo + mc1 * 4];
    *(float4*)&As[0][kr0][mc0*4] = rA0;
    *(float4*)&As[0][kr1][mc1*4] = rA1;
    *(float4*)&Bs[0][kr0][mc0*4] = rB0;
    *(float4*)&Bs[0][kr1][mc1*4] = rB1;
    __syncthreads();

    for (int k0 = 0; k0 < Ee; k0 += 16) {
        int buf = (k0 >> 4) & 1;
        bool more = (k0 + 16) < Ee;
        if (more) {
            int kn = k0 + 16;
            rA0 = *(const float4*)&P[(size_t)(kn + kr0) * Ee + m0 + mc0 * 4];
            rA1 = *(const float4*)&P[(size_t)(kn + kr1) * Ee + m0 + mc1 * 4];
            rB0 = *(const float4*)&B[(size_t)(kn + kr0) * Oo + mc0 * 4];
            rB1 = *(const float4*)&B[(size_t)(kn + kr1) * Oo + mc1 * 4];
        }
#pragma unroll
        for (int kk = 0; kk < 16; kk++) {
            float4 a0 = *(float4*)&As[buf][kk][ty * 8];
            float4 a1 = *(float4*)&As[buf][kk][ty * 8 + 4];
            float4 b0 = *(float4*)&Bs[buf][kk][tx * 8];
            float4 b1 = *(float4*)&Bs[buf][kk][tx * 8 + 4];
            float ra[8] = {a0.x, a0.y, a0.z, a0.w, a1.x, a1.y, a1.z, a1.w};
            float rb[8] = {b0.x, b0.y, b0.z, b0.w, b1.x, b1.y, b1.z, b1.w};
#pragma unroll
            for (int i = 0; i < 8; i++)
#pragma unroll
                for (int j = 0; j < 8; j++) acc[i][j] += ra[i] * rb[j];
        }
        if (more) {
            int nb = buf ^ 1;
            *(float4*)&As[nb][kr0][mc0*4] = rA0;
            *(float4*)&As[nb][kr1][mc1*4] = rA1;
            *(float4*)&Bs[nb][kr0][mc0*4] = rB0;
            *(float4*)&Bs[nb][kr1][mc1*4] = rB1;
            __syncthreads();
        }
    }
#pragma unroll
    for (int i = 0; i < 8; i++) {
        int j = m0 + ty * 8 + i;
#pragma unroll
        for (int jj = 0; jj < 8; jj++) {
            int o = tx * 8 + jj;
            out[(size_t)n * Ee * HO + (size_t)j * HO + h * Oo + o] =
                fmaxf(acc[i][jj], 0.f);
        }
    }
}

// ============================================================================
extern "C" void kernel_launch(void* const* d_in, const int* in_sizes, int n_in,
                              void* d_out, int out_size) {
    const float* input_state = (const float*)d_in[0];
    const int*   adj         = (const int*)d_in[1];
    // d_in[2] = entity_mask (unused by the reference)
    const float* query_vec   = (const float*)d_in[3];
    const float* W           = (const float*)d_in[4];
    const float* a_src       = (const float*)d_in[5];
    const float* a_dst       = (const float*)d_in[6];
    const float* qW1         = (const float*)d_in[7];
    const float* qW2         = (const float*)d_in[8];
    float* out = (float*)d_out;

    gemm1_kernel<<<dim3(64, 1, Hh), 256>>>(input_state, W);
    gate_kernel<<<dim3(Nn, HT), 256>>>(query_vec, qW1, qW2, a_src, a_dst);
    uvec_kernel<<<dim3(Nn, HT), 256>>>(W);
    s12_kernel<<<dim3(8, Nn), 256>>>(input_state);
    attn_kernel<<<dim3(Ee, Nn), 256>>>(adj);
    gemm2_kernel<<<dim3(4, 1, Hh * Nn), 256>>>(out);
}

// round 6
// speedup vs baseline: 2.2918x; 1.6646x over previous
#include <cuda_runtime.h>
#include <cstdint>
#include <math.h>

// Problem constants
#define Nn 16
#define Ee 512
#define Dd 1024
#define Hh 8
#define Tt 2
#define Oo 128
#define HT (Hh*Tt)          // 16
#define HO (Hh*Oo)          // 1024
#define NEGV (-9000000000000000.0f)

// ---------------- scratch (device globals) ----------------------------------
__device__ float g_h[(size_t)Hh * Nn * Ee * Oo];      // 32 MB  h_last [h][n][e][o]
__device__ float g_wt[(size_t)Hh * Oo * Dd];          // 4 MB   W_last^T [h][o][d]
__device__ float g_v1[HT * Nn * Oo];                  // g1*a_src  [ht][n][o]
__device__ float g_v2[HT * Nn * Oo];                  // g2*a_dst
__device__ float g_u[(size_t)Nn * Dd * 32];           // [n][d][c] c: 0-15 u1(ht), 16-31 u2(ht)
__device__ float g_s1[HT * Nn * Ee];                  // [ht][n][e]
__device__ float g_s2[HT * Nn * Ee];
__device__ float g_coefs[(size_t)Hh * Nn * Ee * Ee];  // 128 MB [h][n][i][j]

// ---------------- mma helpers ------------------------------------------------
__device__ __forceinline__ uint32_t f2tf(float x) {
    uint32_t r;
    asm("cvt.rna.tf32.f32 %0, %1;" : "=r"(r) : "f"(x));
    return r;
}

__device__ __forceinline__ void mma_tf32(float* d, const uint32_t* a,
                                         const uint32_t* b) {
    asm volatile(
        "mma.sync.aligned.m16n8k8.row.col.f32.tf32.tf32.f32 "
        "{%0,%1,%2,%3}, {%4,%5,%6,%7}, {%8,%9}, {%0,%1,%2,%3};"
        : "+f"(d[0]), "+f"(d[1]), "+f"(d[2]), "+f"(d[3])
        : "r"(a[0]), "r"(a[1]), "r"(a[2]), "r"(a[3]), "r"(b[0]), "r"(b[1]));
}

// ============================================================================
// Kernel 0: W_last^T: g_wt[h][o][d] = W[h*T + (T-1)][d][o]
// ============================================================================
__global__ void wt_kernel(const float* __restrict__ Wp) {
    __shared__ float t[32][33];
    int h = blockIdx.z;
    int d0 = blockIdx.x * 32, o0 = blockIdx.y * 32;
    const float* src = Wp + (size_t)(h * Tt + (Tt - 1)) * Dd * Oo;
    int x = threadIdx.x, y = threadIdx.y;
#pragma unroll
    for (int yy = y; yy < 32; yy += 8)
        t[yy][x] = src[(size_t)(d0 + yy) * Oo + o0 + x];
    __syncthreads();
#pragma unroll
    for (int yy = y; yy < 32; yy += 8)
        g_wt[((size_t)h * Oo + o0 + yy) * Dd + d0 + x] = t[x][yy];
}

// ============================================================================
// Kernel 1: tf32 mma.sync GEMM: h_last[h][m][o] = sum_d input[m,d]*Wt[h][o][d]
// Block 128x128, 8 warps (4x2), warp tile 32x64, BK=32.
// ============================================================================
__global__ __launch_bounds__(256) void gemm1_mma(const float* __restrict__ A) {
    __shared__ float As[128][36];   // [m][k]
    __shared__ float Bs[128][36];   // [n][k]

    int h = blockIdx.y;
    int m0 = blockIdx.x * 128;
    int tid = threadIdx.x;
    int wid = tid >> 5, lane = tid & 31;
    int wm = wid >> 1, wn = wid & 1;
    int lr = lane >> 2, lc = lane & 3;

    const float* Ab = A + (size_t)m0 * Dd;
    const float* Bb = g_wt + (size_t)h * Oo * Dd;

    float d[2][8][4] = {};

    for (int kb = 0; kb < Dd; kb += 32) {
#pragma unroll
        for (int l = 0; l < 4; l++) {
            int fid = tid + l * 256;
            int row = fid >> 3, c4 = fid & 7;
            *(float4*)&As[row][c4 * 4] =
                *(const float4*)&Ab[(size_t)row * Dd + kb + c4 * 4];
            *(float4*)&Bs[row][c4 * 4] =
                *(const float4*)&Bb[(size_t)row * Dd + kb + c4 * 4];
        }
        __syncthreads();
#pragma unroll
        for (int kk = 0; kk < 4; kk++) {
            int k8 = kk * 8;
            uint32_t af[2][4];
#pragma unroll
            for (int mi = 0; mi < 2; mi++) {
                int rr = wm * 32 + mi * 16 + lr;
                af[mi][0] = f2tf(As[rr][k8 + lc]);
                af[mi][1] = f2tf(As[rr + 8][k8 + lc]);
                af[mi][2] = f2tf(As[rr][k8 + 4 + lc]);
                af[mi][3] = f2tf(As[rr + 8][k8 + 4 + lc]);
            }
            uint32_t bf[8][2];
#pragma unroll
            for (int ni = 0; ni < 8; ni++) {
                int nn = wn * 64 + ni * 8 + lr;
                bf[ni][0] = f2tf(Bs[nn][k8 + lc]);
                bf[ni][1] = f2tf(Bs[nn][k8 + 4 + lc]);
            }
#pragma unroll
            for (int mi = 0; mi < 2; mi++)
#pragma unroll
                for (int ni = 0; ni < 8; ni++)
                    mma_tf32(d[mi][ni], af[mi], bf[ni]);
        }
        __syncthreads();
    }

    float* C = g_h + ((size_t)h * (Nn * Ee) + m0) * Oo;
#pragma unroll
    for (int mi = 0; mi < 2; mi++) {
        int r = wm * 32 + mi * 16 + lr;
#pragma unroll
        for (int ni = 0; ni < 8; ni++) {
            int c = wn * 64 + ni * 8 + 2 * lc;
            *(float2*)&C[(size_t)r * Oo + c] =
                make_float2(d[mi][ni][0], d[mi][ni][1]);
            *(float2*)&C[(size_t)(r + 8) * Oo + c] =
                make_float2(d[mi][ni][2], d[mi][ni][3]);
        }
    }
}

// ============================================================================
// Kernel 2: query-gate MLP -> v1 = g1*a_src, v2 = g2*a_dst  (per ht,n)
// ============================================================================
__global__ __launch_bounds__(256) void gate_kernel(const float* __restrict__ qvec,
                                                   const float* __restrict__ qW1,
                                                   const float* __restrict__ qW2,
                                                   const float* __restrict__ a_src,
                                                   const float* __restrict__ a_dst) {
    int n = blockIdx.x;
    int ht = blockIdx.y;
    __shared__ float qv[1024];
    __shared__ float tmp[256];
    int tid = threadIdx.x;

    for (int i = tid; i < 1024; i += 256) qv[i] = qvec[n * 1024 + i];
    __syncthreads();

    const float* w1 = qW1 + (size_t)ht * 1024 * 256;
    float s = 0.f;
    for (int q = 0; q < 1024; q++) s += qv[q] * w1[(size_t)q * 256 + tid];
    tmp[tid] = fmaxf(s, 0.f);
    __syncthreads();

    const float* w2 = qW2 + (size_t)ht * 256 * 256;
    float s2 = 0.f;
    for (int c = 0; c < 256; c++) s2 += tmp[c] * w2[c * 256 + tid];
    float g = 1.f / (1.f + expf(-s2));

    int base = (ht * Nn + n) * Oo;
    if (tid < 128) g_v1[base + tid] = g * a_src[ht * Oo + tid];
    else           g_v2[base + (tid - 128)] = g * a_dst[ht * Oo + (tid - 128)];
}

// ============================================================================
// Kernel 3: u[n][d][ht] = sum_o W[ht][d][o]*v1[ht][n][o];  [16+ht] with v2
// ============================================================================
__global__ __launch_bounds__(256) void uvec_kernel(const float* __restrict__ Wp) {
    int n = blockIdx.x, ht = blockIdx.y;
    __shared__ float v1s[128], v2s[128];
    int tid = threadIdx.x;
    if (tid < 128) v1s[tid] = g_v1[(ht * Nn + n) * Oo + tid];
    else           v2s[tid - 128] = g_v2[(ht * Nn + n) * Oo + (tid - 128)];
    __syncthreads();

    int warp = tid >> 5, lane = tid & 31;
    const float* Wh = Wp + (size_t)ht * Dd * Oo;
    for (int d = warp; d < Dd; d += 8) {
        const float* wr = Wh + (size_t)d * Oo;
        float s1 = 0.f, s2 = 0.f;
#pragma unroll
        for (int c = lane; c < 128; c += 32) {
            float w = wr[c];
            s1 += w * v1s[c];
            s2 += w * v2s[c];
        }
#pragma unroll
        for (int off = 16; off; off >>= 1) {
            s1 += __shfl_down_sync(0xffffffffu, s1, off);
            s2 += __shfl_down_sync(0xffffffffu, s2, off);
        }
        if (lane == 0) {
            g_u[((size_t)n * Dd + d) * 32 + ht] = s1;
            g_u[((size_t)n * Dd + d) * 32 + 16 + ht] = s2;
        }
    }
}

// ============================================================================
// Kernel 4: S[n] = input[n] (E x D) @ U[n] (D x 32) -> g_s1/g_s2
// e-tile 32, grid (16, Nn) = 256 blocks
// ============================================================================
__global__ __launch_bounds__(256) void s12_kernel(const float* __restrict__ A) {
    int e0 = blockIdx.x * 32;
    int n = blockIdx.y;
    __shared__ float inT[32][68];
    __shared__ float Ut[64][36];

    int tid = threadIdx.x;
    int e = tid >> 3, g = tid & 7;   // 32 e x 8 groups of 4 cols
    float acc[4] = {};

    for (int d0 = 0; d0 < Dd; d0 += 64) {
#pragma unroll
        for (int l = 0; l < 2; l++) {
            int fid = tid + l * 256;
            int row = fid >> 4, c4 = fid & 15;
            *(float4*)&inT[row][c4 * 4] =
                *(const float4*)&A[((size_t)n * Ee + e0 + row) * Dd + d0 + c4 * 4];
        }
#pragma unroll
        for (int l = 0; l < 2; l++) {
            int fid = tid + l * 256;
            int row = fid >> 3, c4 = fid & 7;
            *(float4*)&Ut[row][c4 * 4] =
                *(const float4*)&g_u[((size_t)n * Dd + d0 + row) * 32 + c4 * 4];
        }
        __syncthreads();
#pragma unroll 16
        for (int d = 0; d < 64; d++) {
            float iv = inT[e][d];
            float4 u = *(float4*)&Ut[d][g * 4];
            acc[0] += iv * u.x; acc[1] += iv * u.y;
            acc[2] += iv * u.z; acc[3] += iv * u.w;
        }
        __syncthreads();
    }
#pragma unroll
    for (int k = 0; k < 4; k++) {
        int cc = g * 4 + k;
        if (cc < 16) g_s1[(cc * Nn + n) * Ee + e0 + e] = acc[k];
        else         g_s2[((cc - 16) * Nn + n) * Ee + e0 + e] = acc[k];
    }
}

// ============================================================================
// Kernel 5: scores + softmax -> coefs[h][n][i][j].  Warp-per-head.
// ============================================================================
__global__ __launch_bounds__(256) void attn_kernel(const int* __restrict__ adj) {
    int i = blockIdx.x;
    int n = blockIdx.y;
    int tid = threadIdx.x;

    __shared__ int   adjs[Ee];
    __shared__ float s2s[HT][Ee];
    __shared__ float s1v[HT];

    adjs[tid]       = adj[((size_t)n * Ee + i) * Ee + tid];
    adjs[tid + 256] = adj[((size_t)n * Ee + i) * Ee + tid + 256];
    for (int idx = tid; idx < HT * Ee; idx += 256) {
        int ht = idx >> 9, j = idx & 511;
        s2s[ht][j] = g_s2[(ht * Nn + n) * Ee + j];
    }
    if (tid < HT) s1v[tid] = g_s1[(tid * Nn + n) * Ee + i];
    __syncthreads();

    int h = tid >> 5, lane = tid & 31;
    float sc[16];
    float m = -INFINITY;
#pragma unroll
    for (int k = 0; k < 16; k++) {
        int j = lane + k * 32;
        int a = adjs[j];
        float x;
        if (a == 0) x = NEGV;
        else {
            int ht = h * Tt + (a - 1);
            float v = s1v[ht] + s2s[ht][j];
            x = v > 0.f ? v : 0.2f * v;
        }
        sc[k] = x;
        m = fmaxf(m, x);
    }
#pragma unroll
    for (int off = 16; off; off >>= 1)
        m = fmaxf(m, __shfl_xor_sync(0xffffffffu, m, off));
    float sum = 0.f;
#pragma unroll
    for (int k = 0; k < 16; k++) {
        float e = __expf(sc[k] - m);
        sc[k] = e;
        sum += e;
    }
#pragma unroll
    for (int off = 16; off; off >>= 1)
        sum += __shfl_xor_sync(0xffffffffu, sum, off);
    float inv = 1.f / sum;
    float* dst = &g_coefs[(((size_t)h * Nn + n) * Ee + i) * Ee];
#pragma unroll
    for (int k = 0; k < 16; k++)
        dst[lane + k * 32] = sc[k] * inv;
}

// ============================================================================
// Kernel 6: out[n][j][h*128+o] = relu( sum_i coefs[h][n][i][j]*hlast[h][n][i][o] )
// tf32 mma.sync; A = coefs^T (transposed on smem store), B = h_last rows.
// ============================================================================
__global__ __launch_bounds__(256) void gemm2_mma(float* __restrict__ out) {
    __shared__ float As[128][36];    // [j][k]
    __shared__ float Bs[32][132];    // [k][o]

    int z = blockIdx.z;
    int h = z >> 4, n = z & 15;
    const float* P = g_coefs + ((size_t)(h * Nn + n)) * Ee * Ee;   // [i][j]
    const float* B = g_h + ((size_t)(h * Nn + n)) * Ee * Oo;       // [i][o]
    int m0 = blockIdx.x * 128;

    int tid = threadIdx.x;
    int wid = tid >> 5, lane = tid & 31;
    int wm = wid >> 1, wn = wid & 1;
    int lr = lane >> 2, lc = lane & 3;

    float d[2][8][4] = {};

    for (int kb = 0; kb < Ee; kb += 32) {
#pragma unroll
        for (int l = 0; l < 4; l++) {
            int fid = tid + l * 256;
            int kk = fid >> 5, c4 = fid & 31;
            float4 v = *(const float4*)&P[(size_t)(kb + kk) * Ee + m0 + c4 * 4];
            As[c4 * 4 + 0][kk] = v.x;
            As[c4 * 4 + 1][kk] = v.y;
            As[c4 * 4 + 2][kk] = v.z;
            As[c4 * 4 + 3][kk] = v.w;
            *(float4*)&Bs[kk][c4 * 4] =
                *(const float4*)&B[(size_t)(kb + kk) * Oo + c4 * 4];
        }
        __syncthreads();
#pragma unroll
        for (int kk = 0; kk < 4; kk++) {
            int k8 = kk * 8;
            uint32_t af[2][4];
#pragma unroll
            for (int mi = 0; mi < 2; mi++) {
                int rr = wm * 32 + mi * 16 + lr;
                af[mi][0] = f2tf(As[rr][k8 + lc]);
                af[mi][1] = f2tf(As[rr + 8][k8 + lc]);
                af[mi][2] = f2tf(As[rr][k8 + 4 + lc]);
                af[mi][3] = f2tf(As[rr + 8][k8 + 4 + lc]);
            }
            uint32_t bf[8][2];
#pragma unroll
            for (int ni = 0; ni < 8; ni++) {
                int nn = wn * 64 + ni * 8 + lr;
                bf[ni][0] = f2tf(Bs[k8 + lc][nn]);
                bf[ni][1] = f2tf(Bs[k8 + 4 + lc][nn]);
            }
#pragma unroll
            for (int mi = 0; mi < 2; mi++)
#pragma unroll
                for (int ni = 0; ni < 8; ni++)
                    mma_tf32(d[mi][ni], af[mi], bf[ni]);
        }
        __syncthreads();
    }

    float* Ob = out + (size_t)n * Ee * HO + h * Oo;
#pragma unroll
    for (int mi = 0; mi < 2; mi++) {
        int j = m0 + wm * 32 + mi * 16 + lr;
#pragma unroll
        for (int ni = 0; ni < 8; ni++) {
            int c = wn * 64 + ni * 8 + 2 * lc;
            *(float2*)&Ob[(size_t)j * HO + c] =
                make_float2(fmaxf(d[mi][ni][0], 0.f), fmaxf(d[mi][ni][1], 0.f));
            *(float2*)&Ob[(size_t)(j + 8) * HO + c] =
                make_float2(fmaxf(d[mi][ni][2], 0.f), fmaxf(d[mi][ni][3], 0.f));
        }
    }
}

// ============================================================================
extern "C" void kernel_launch(void* const* d_in, const int* in_sizes, int n_in,
                              void* d_out, int out_size) {
    const float* input_state = (const float*)d_in[0];
    const int*   adj         = (const int*)d_in[1];
    const float* query_vec   = (const float*)d_in[3];
    const float* W           = (const float*)d_in[4];
    const float* a_src       = (const float*)d_in[5];
    const float* a_dst       = (const float*)d_in[6];
    const float* qW1         = (const float*)d_in[7];
    const float* qW2         = (const float*)d_in[8];
    float* out = (float*)d_out;

    wt_kernel<<<dim3(32, 4, Hh), dim3(32, 8)>>>(W);
    gemm1_mma<<<dim3(64, Hh), 256>>>(input_state);
    gate_kernel<<<dim3(Nn, HT), 256>>>(query_vec, qW1, qW2, a_src, a_dst);
    uvec_kernel<<<dim3(Nn, HT), 256>>>(W);
    s12_kernel<<<dim3(16, Nn), 256>>>(input_state);
    attn_kernel<<<dim3(Ee, Nn), 256>>>(adj);
    gemm2_mma<<<dim3(4, 1, Hh * Nn), 256>>>(out);
}

// round 7
// speedup vs baseline: 2.6489x; 1.1558x over previous
#include <cuda_runtime.h>
#include <cstdint>
#include <math.h>

// Problem constants
#define Nn 16
#define Ee 512
#define Dd 1024
#define Hh 8
#define Tt 2
#define Oo 128
#define HT (Hh*Tt)          // 16
#define HO (Hh*Oo)          // 1024
#define NEGV (-9000000000000000.0f)

// ---------------- scratch (device globals) ----------------------------------
__device__ float g_h[(size_t)Hh * Nn * Ee * Oo];      // 32 MB  h_last [h][n][e][o] (tf32-rounded)
__device__ float g_wt[(size_t)Hh * Oo * Dd];          // 4 MB   W_last^T [h][o][d] (tf32-rounded)
__device__ float g_v1[HT * Nn * Oo];                  // g1*a_src  [ht][n][o]
__device__ float g_v2[HT * Nn * Oo];                  // g2*a_dst
__device__ float g_u[(size_t)Nn * Dd * 32];           // [n][d][c] c: 0-15 u1(ht), 16-31 u2(ht)
__device__ float g_s1[HT * Nn * Ee];                  // [ht][n][e]
__device__ float g_s2[HT * Nn * Ee];
__device__ float g_coefs[(size_t)Hh * Nn * Ee * Ee];  // 128 MB [h][n][i][j] (tf32-rounded)

// ---------------- mma helpers ------------------------------------------------
__device__ __forceinline__ uint32_t f2tf(float x) {
    uint32_t r;
    asm("cvt.rna.tf32.f32 %0, %1;" : "=r"(r) : "f"(x));
    return r;
}

__device__ __forceinline__ void mma_tf32(float* d, const uint32_t* a,
                                         const uint32_t* b) {
    asm volatile(
        "mma.sync.aligned.m16n8k8.row.col.f32.tf32.tf32.f32 "
        "{%0,%1,%2,%3}, {%4,%5,%6,%7}, {%8,%9}, {%0,%1,%2,%3};"
        : "+f"(d[0]), "+f"(d[1]), "+f"(d[2]), "+f"(d[3])
        : "r"(a[0]), "r"(a[1]), "r"(a[2]), "r"(a[3]), "r"(b[0]), "r"(b[1]));
}

// ============================================================================
// Kernel 0: W_last^T (tf32-rounded): g_wt[h][o][d] = rna(W[h*T+T-1][d][o])
// ============================================================================
__global__ void wt_kernel(const float* __restrict__ Wp) {
    __shared__ float t[32][33];
    int h = blockIdx.z;
    int d0 = blockIdx.x * 32, o0 = blockIdx.y * 32;
    const float* src = Wp + (size_t)(h * Tt + (Tt - 1)) * Dd * Oo;
    int x = threadIdx.x, y = threadIdx.y;
#pragma unroll
    for (int yy = y; yy < 32; yy += 8)
        t[yy][x] = src[(size_t)(d0 + yy) * Oo + o0 + x];
    __syncthreads();
#pragma unroll
    for (int yy = y; yy < 32; yy += 8)
        g_wt[((size_t)h * Oo + o0 + yy) * Dd + d0 + x] =
            __uint_as_float(f2tf(t[x][yy]));
}

// ============================================================================
// Kernel 1: tf32 mma.sync GEMM: h_last[h][m][o] = sum_d input[m,d]*Wt[h][o][d]
// B-fragments pre-rounded (no cvt); epilogue stores tf32-rounded h.
// ============================================================================
__global__ __launch_bounds__(256) void gemm1_mma(const float* __restrict__ A) {
    __shared__ float As[128][36];   // [m][k]
    __shared__ float Bs[128][36];   // [n][k]

    int h = blockIdx.y;
    int m0 = blockIdx.x * 128;
    int tid = threadIdx.x;
    int wid = tid >> 5, lane = tid & 31;
    int wm = wid >> 1, wn = wid & 1;
    int lr = lane >> 2, lc = lane & 3;

    const float* Ab = A + (size_t)m0 * Dd;
    const float* Bb = g_wt + (size_t)h * Oo * Dd;

    float d[2][8][4] = {};

    for (int kb = 0; kb < Dd; kb += 32) {
#pragma unroll
        for (int l = 0; l < 4; l++) {
            int fid = tid + l * 256;
            int row = fid >> 3, c4 = fid & 7;
            *(float4*)&As[row][c4 * 4] =
                *(const float4*)&Ab[(size_t)row * Dd + kb + c4 * 4];
            *(float4*)&Bs[row][c4 * 4] =
                *(const float4*)&Bb[(size_t)row * Dd + kb + c4 * 4];
        }
        __syncthreads();
#pragma unroll
        for (int kk = 0; kk < 4; kk++) {
            int k8 = kk * 8;
            uint32_t af[2][4];
#pragma unroll
            for (int mi = 0; mi < 2; mi++) {
                int rr = wm * 32 + mi * 16 + lr;
                af[mi][0] = f2tf(As[rr][k8 + lc]);
                af[mi][1] = f2tf(As[rr + 8][k8 + lc]);
                af[mi][2] = f2tf(As[rr][k8 + 4 + lc]);
                af[mi][3] = f2tf(As[rr + 8][k8 + 4 + lc]);
            }
            uint32_t bf[8][2];
#pragma unroll
            for (int ni = 0; ni < 8; ni++) {
                int nn = wn * 64 + ni * 8 + lr;
                bf[ni][0] = __float_as_uint(Bs[nn][k8 + lc]);
                bf[ni][1] = __float_as_uint(Bs[nn][k8 + 4 + lc]);
            }
#pragma unroll
            for (int mi = 0; mi < 2; mi++)
#pragma unroll
                for (int ni = 0; ni < 8; ni++)
                    mma_tf32(d[mi][ni], af[mi], bf[ni]);
        }
        __syncthreads();
    }

    float* C = g_h + ((size_t)h * (Nn * Ee) + m0) * Oo;
#pragma unroll
    for (int mi = 0; mi < 2; mi++) {
        int r = wm * 32 + mi * 16 + lr;
#pragma unroll
        for (int ni = 0; ni < 8; ni++) {
            int c = wn * 64 + ni * 8 + 2 * lc;
            *(float2*)&C[(size_t)r * Oo + c] =
                make_float2(__uint_as_float(f2tf(d[mi][ni][0])),
                            __uint_as_float(f2tf(d[mi][ni][1])));
            *(float2*)&C[(size_t)(r + 8) * Oo + c] =
                make_float2(__uint_as_float(f2tf(d[mi][ni][2])),
                            __uint_as_float(f2tf(d[mi][ni][3])));
        }
    }
}

// ============================================================================
// Kernel 2: query-gate MLP, batched over 8 n per block.  Streams qW1 once.
// grid (2, HT); smem: qvs[1024][8] (transposed), tmps[256][8].
// ============================================================================
__global__ __launch_bounds__(256) void gate_kernel(const float* __restrict__ qvec,
                                                   const float* __restrict__ qW1,
                                                   const float* __restrict__ qW2,
                                                   const float* __restrict__ a_src,
                                                   const float* __restrict__ a_dst) {
    __shared__ float qvs[1024][8];   // [q][nn]
    __shared__ float tmps[256][8];   // [c][nn]
    int n0 = blockIdx.x * 8;
    int ht = blockIdx.y;
    int tid = threadIdx.x;

    // load 8 query vectors, transposed
    for (int l = 0; l < 32; l++) {
        int idx = l * 256 + tid;          // 8192 total
        int nn = idx >> 10, q = idx & 1023;
        qvs[q][nn] = qvec[(size_t)(n0 + nn) * 1024 + q];
    }
    __syncthreads();

    // layer 1: tmp[nn][c=tid] = relu( sum_q qv[nn][q] * w1[q][c] )
    const float* w1 = qW1 + (size_t)ht * 1024 * 256;
    float acc[8] = {};
    for (int q = 0; q < 1024; q++) {
        float w = w1[(size_t)q * 256 + tid];
        float4 a = *(float4*)&qvs[q][0];
        float4 b = *(float4*)&qvs[q][4];
        acc[0] += w * a.x; acc[1] += w * a.y; acc[2] += w * a.z; acc[3] += w * a.w;
        acc[4] += w * b.x; acc[5] += w * b.y; acc[6] += w * b.z; acc[7] += w * b.w;
    }
#pragma unroll
    for (int k = 0; k < 8; k++) tmps[tid][k] = fmaxf(acc[k], 0.f);
    __syncthreads();

    // layer 2: g[nn][c=tid] = sigmoid( sum_c2 tmp[nn][c2] * w2[c2][c] )
    const float* w2 = qW2 + (size_t)ht * 256 * 256;
    float acc2[8] = {};
    for (int c2 = 0; c2 < 256; c2++) {
        float w = w2[(size_t)c2 * 256 + tid];
        float4 a = *(float4*)&tmps[c2][0];
        float4 b = *(float4*)&tmps[c2][4];
        acc2[0] += w * a.x; acc2[1] += w * a.y; acc2[2] += w * a.z; acc2[3] += w * a.w;
        acc2[4] += w * b.x; acc2[5] += w * b.y; acc2[6] += w * b.z; acc2[7] += w * b.w;
    }

    float av = (tid < 128) ? a_src[ht * Oo + tid] : a_dst[ht * Oo + (tid - 128)];
    int o = tid & 127;
#pragma unroll
    for (int nn = 0; nn < 8; nn++) {
        float g = 1.f / (1.f + __expf(-acc2[nn]));
        float val = g * av;
        int base = (ht * Nn + n0 + nn) * Oo + o;
        if (tid < 128) g_v1[base] = val;
        else           g_v2[base] = val;
    }
}

// ============================================================================
// Kernel 3 (rewritten): u columns via smem-tiled mini-GEMM.
// Block per (32-row d-tile, ht): computes u1/u2 for all 16 n.
// ============================================================================
__global__ __launch_bounds__(256) void uvec_kernel(const float* __restrict__ Wp) {
    __shared__ float Ws[32][132];    // [d_local][o]
    __shared__ float vsT[128][36];   // [o][c]  c = n*2 + sel
    int d0 = blockIdx.x * 32;
    int ht = blockIdx.y;
    int tid = threadIdx.x;

    // load v1/v2 transposed: 32 c x 128 o
#pragma unroll
    for (int l = 0; l < 16; l++) {
        int idx = l * 256 + tid;       // 4096
        int c = idx >> 7, o = idx & 127;
        int n = c >> 1;
        const float* src = (c & 1) ? g_v2 : g_v1;
        vsT[o][c] = src[(ht * Nn + n) * Oo + o];
    }
    // load W tile [32][128]
    const float* Wh = Wp + (size_t)ht * Dd * Oo + (size_t)d0 * Oo;
#pragma unroll
    for (int l = 0; l < 16; l++) {
        int idx = l * 256 + tid;
        int r = idx >> 7, o = idx & 127;
        Ws[r][o] = Wh[(size_t)r * Oo + o];
    }
    __syncthreads();

    int dl = tid >> 3, c4 = tid & 7;   // 32 d x 8 col-groups of 4
    float acc[4] = {};
#pragma unroll 8
    for (int o = 0; o < 128; o++) {
        float w = Ws[dl][o];
        float4 v = *(float4*)&vsT[o][c4 * 4];
        acc[0] += w * v.x; acc[1] += w * v.y;
        acc[2] += w * v.z; acc[3] += w * v.w;
    }
#pragma unroll
    for (int k = 0; k < 4; k++) {
        int c = c4 * 4 + k;
        int n = c >> 1, sel = c & 1;
        g_u[((size_t)n * Dd + d0 + dl) * 32 + sel * 16 + ht] = acc[k];
    }
}

// ============================================================================
// Kernel 4: S[n] = input[n] (E x D) @ U[n] (D x 32) -> g_s1/g_s2
// ============================================================================
__global__ __launch_bounds__(256) void s12_kernel(const float* __restrict__ A) {
    int e0 = blockIdx.x * 32;
    int n = blockIdx.y;
    __shared__ float inT[32][68];
    __shared__ float Ut[64][36];

    int tid = threadIdx.x;
    int e = tid >> 3, g = tid & 7;
    float acc[4] = {};

    for (int d0 = 0; d0 < Dd; d0 += 64) {
#pragma unroll
        for (int l = 0; l < 2; l++) {
            int fid = tid + l * 256;
            int row = fid >> 4, c4 = fid & 15;
            *(float4*)&inT[row][c4 * 4] =
                *(const float4*)&A[((size_t)n * Ee + e0 + row) * Dd + d0 + c4 * 4];
        }
#pragma unroll
        for (int l = 0; l < 2; l++) {
            int fid = tid + l * 256;
            int row = fid >> 3, c4 = fid & 7;
            *(float4*)&Ut[row][c4 * 4] =
                *(const float4*)&g_u[((size_t)n * Dd + d0 + row) * 32 + c4 * 4];
        }
        __syncthreads();
#pragma unroll 16
        for (int d = 0; d < 64; d++) {
            float iv = inT[e][d];
            float4 u = *(float4*)&Ut[d][g * 4];
            acc[0] += iv * u.x; acc[1] += iv * u.y;
            acc[2] += iv * u.z; acc[3] += iv * u.w;
        }
        __syncthreads();
    }
#pragma unroll
    for (int k = 0; k < 4; k++) {
        int cc = g * 4 + k;
        if (cc < 16) g_s1[(cc * Nn + n) * Ee + e0 + e] = acc[k];
        else         g_s2[((cc - 16) * Nn + n) * Ee + e0 + e] = acc[k];
    }
}

// ============================================================================
// Kernel 5: scores + softmax -> coefs (tf32-rounded).  Warp-per-head.
// ============================================================================
__global__ __launch_bounds__(256) void attn_kernel(const int* __restrict__ adj) {
    int i = blockIdx.x;
    int n = blockIdx.y;
    int tid = threadIdx.x;

    __shared__ int   adjs[Ee];
    __shared__ float s2s[HT][Ee];
    __shared__ float s1v[HT];

    adjs[tid]       = adj[((size_t)n * Ee + i) * Ee + tid];
    adjs[tid + 256] = adj[((size_t)n * Ee + i) * Ee + tid + 256];
    for (int idx = tid; idx < HT * Ee; idx += 256) {
        int ht = idx >> 9, j = idx & 511;
        s2s[ht][j] = g_s2[(ht * Nn + n) * Ee + j];
    }
    if (tid < HT) s1v[tid] = g_s1[(tid * Nn + n) * Ee + i];
    __syncthreads();

    int h = tid >> 5, lane = tid & 31;
    float sc[16];
    float m = -INFINITY;
#pragma unroll
    for (int k = 0; k < 16; k++) {
        int j = lane + k * 32;
        int a = adjs[j];
        float x;
        if (a == 0) x = NEGV;
        else {
            int ht = h * Tt + (a - 1);
            float v = s1v[ht] + s2s[ht][j];
            x = v > 0.f ? v : 0.2f * v;
        }
        sc[k] = x;
        m = fmaxf(m, x);
    }
#pragma unroll
    for (int off = 16; off; off >>= 1)
        m = fmaxf(m, __shfl_xor_sync(0xffffffffu, m, off));
    float sum = 0.f;
#pragma unroll
    for (int k = 0; k < 16; k++) {
        float e = __expf(sc[k] - m);
        sc[k] = e;
        sum += e;
    }
#pragma unroll
    for (int off = 16; off; off >>= 1)
        sum += __shfl_xor_sync(0xffffffffu, sum, off);
    float inv = 1.f / sum;
    float* dst = &g_coefs[(((size_t)h * Nn + n) * Ee + i) * Ee];
#pragma unroll
    for (int k = 0; k < 16; k++)
        dst[lane + k * 32] = __uint_as_float(f2tf(sc[k] * inv));
}

// ============================================================================
// Kernel 6: out = relu(coefs^T @ h_last).  All operands pre-rounded: no cvt.
// ============================================================================
__global__ __launch_bounds__(256) void gemm2_mma(float* __restrict__ out) {
    __shared__ float As[128][36];    // [j][k]
    __shared__ float Bs[32][132];    // [k][o]

    int z = blockIdx.z;
    int h = z >> 4, n = z & 15;
    const float* P = g_coefs + ((size_t)(h * Nn + n)) * Ee * Ee;
    const float* B = g_h + ((size_t)(h * Nn + n)) * Ee * Oo;
    int m0 = blockIdx.x * 128;

    int tid = threadIdx.x;
    int wid = tid >> 5, lane = tid & 31;
    int wm = wid >> 1, wn = wid & 1;
    int lr = lane >> 2, lc = lane & 3;

    float d[2][8][4] = {};

    for (int kb = 0; kb < Ee; kb += 32) {
#pragma unroll
        for (int l = 0; l < 4; l++) {
            int fid = tid + l * 256;
            int kk = fid >> 5, c4 = fid & 31;
            float4 v = *(const float4*)&P[(size_t)(kb + kk) * Ee + m0 + c4 * 4];
            As[c4 * 4 + 0][kk] = v.x;
            As[c4 * 4 + 1][kk] = v.y;
            As[c4 * 4 + 2][kk] = v.z;
            As[c4 * 4 + 3][kk] = v.w;
            *(float4*)&Bs[kk][c4 * 4] =
                *(const float4*)&B[(size_t)(kb + kk) * Oo + c4 * 4];
        }
        __syncthreads();
#pragma unroll
        for (int kk = 0; kk < 4; kk++) {
            int k8 = kk * 8;
            uint32_t af[2][4];
#pragma unroll
            for (int mi = 0; mi < 2; mi++) {
                int rr = wm * 32 + mi * 16 + lr;
                af[mi][0] = __float_as_uint(As[rr][k8 + lc]);
                af[mi][1] = __float_as_uint(As[rr + 8][k8 + lc]);
                af[mi][2] = __float_as_uint(As[rr][k8 + 4 + lc]);
                af[mi][3] = __float_as_uint(As[rr + 8][k8 + 4 + lc]);
            }
            uint32_t bf[8][2];
#pragma unroll
            for (int ni = 0; ni < 8; ni++) {
                int nn = wn * 64 + ni * 8 + lr;
                bf[ni][0] = __float_as_uint(Bs[k8 + lc][nn]);
                bf[ni][1] = __float_as_uint(Bs[k8 + 4 + lc][nn]);
            }
#pragma unroll
            for (int mi = 0; mi < 2; mi++)
#pragma unroll
                for (int ni = 0; ni < 8; ni++)
                    mma_tf32(d[mi][ni], af[mi], bf[ni]);
        }
        __syncthreads();
    }

    float* Ob = out + (size_t)n * Ee * HO + h * Oo;
#pragma unroll
    for (int mi = 0; mi < 2; mi++) {
        int j = m0 + wm * 32 + mi * 16 + lr;
#pragma unroll
        for (int ni = 0; ni < 8; ni++) {
            int c = wn * 64 + ni * 8 + 2 * lc;
            *(float2*)&Ob[(size_t)j * HO + c] =
                make_float2(fmaxf(d[mi][ni][0], 0.f), fmaxf(d[mi][ni][1], 0.f));
            *(float2*)&Ob[(size_t)(j + 8) * HO + c] =
                make_float2(fmaxf(d[mi][ni][2], 0.f), fmaxf(d[mi][ni][3], 0.f));
        }
    }
}

// ============================================================================
extern "C" void kernel_launch(void* const* d_in, const int* in_sizes, int n_in,
                              void* d_out, int out_size) {
    const float* input_state = (const float*)d_in[0];
    const int*   adj         = (const int*)d_in[1];
    const float* query_vec   = (const float*)d_in[3];
    const float* W           = (const float*)d_in[4];
    const float* a_src       = (const float*)d_in[5];
    const float* a_dst       = (const float*)d_in[6];
    const float* qW1         = (const float*)d_in[7];
    const float* qW2         = (const float*)d_in[8];
    float* out = (float*)d_out;

    wt_kernel<<<dim3(32, 4, Hh), dim3(32, 8)>>>(W);
    gemm1_mma<<<dim3(64, Hh), 256>>>(input_state);
    gate_kernel<<<dim3(2, HT), 256>>>(query_vec, qW1, qW2, a_src, a_dst);
    uvec_kernel<<<dim3(32, HT), 256>>>(W);
    s12_kernel<<<dim3(16, Nn), 256>>>(input_state);
    attn_kernel<<<dim3(Ee, Nn), 256>>>(adj);
    gemm2_mma<<<dim3(4, 1, Hh * Nn), 256>>>(out);
}